// round 16
// baseline (speedup 1.0000x reference)
#include <cuda_runtime.h>
#include <cstdint>
#include <cstddef>

#define DEV static __device__ __forceinline__

constexpr int Bb = 16, Ll = 8192;
constexpr int NBLK = 152;              // flat blocks (= GB300 SM count)
constexpr int NSLOT = NBLK * 2;        // kv partial slots (2 per block)
constexpr int NT = 1024;               // total (batch, l-tile) units: 16*64
constexpr float SCALE = 0.08838834764831845f; // 1/sqrt(128)
constexpr int TS = 136;    // k-major smem tile row stride (floats)
constexpr int TSV = 132;   // n-major (V) smem tile row stride (floats)
constexpr int TILE_B = 128 * TS * 4;   // 69632 bytes
constexpr int TILEV_B = 128 * TSV * 4; // 67584 bytes

// ---------------- scratch (device globals; no allocation) ----------------
__device__ __align__(16) float g_kvpart[(size_t)NSLOT * 16384];
__device__ __align__(16) float g_kspart[NSLOT * 128];
__device__ int g_kvtag[NSLOT];
__device__ __align__(16) float g_kv[Bb * 128 * 128];  // kv: [b][m][v] (tf32-rounded)
__device__ __align__(16) float g_ksum[Bb * 128];

// ---------------- helpers ----------------
DEV float rna(float x) { uint32_t r; asm("cvt.rna.tf32.f32 %0,%1;" : "=r"(r) : "f"(x)); return __uint_as_float(r); }
DEV float rcp_nr(float x) { float r; asm("rcp.approx.f32 %0,%1;" : "=f"(r) : "f"(x)); return r * (2.0f - x * r); }
DEV void cp16(uint32_t s, const void *g) { asm volatile("cp.async.ca.shared.global [%0],[%1],16;" :: "r"(s), "l"(g)); }
DEV void cpcommit() { asm volatile("cp.async.commit_group;"); }
template <int N> DEV void cpwait() { asm volatile("cp.async.wait_group %0;" :: "n"(N)); }

// m16n8k8 tf32 mma (legal on compute_103; runs on the tensor pipe)
DEV void mma8(float *d, const uint32_t *a, const uint32_t *b) {
    asm volatile("mma.sync.aligned.m16n8k8.row.col.f32.tf32.tf32.f32 "
                 "{%0,%1,%2,%3}, {%4,%5,%6,%7}, {%8,%9}, {%0,%1,%2,%3};"
                 : "+f"(d[0]), "+f"(d[1]), "+f"(d[2]), "+f"(d[3])
                 : "r"(a[0]), "r"(a[1]), "r"(a[2]), "r"(a[3]), "r"(b[0]), "r"(b[1]));
}

// Load 128x128 fp32 tile (global row stride gs floats) -> smem rows of stride ss.
// 512 threads, 8 x cp16 each.
DEV void load_tile(uint32_t sb, const float *g, size_t gs, int ss) {
    int t = threadIdx.x, c4 = t & 31, r0 = t >> 5;
#pragma unroll
    for (int i = 0; i < 8; i++) {
        int row = i * 16 + r0;
        cp16(sb + (uint32_t)(row * ss * 4) + (uint32_t)c4 * 16, g + (size_t)row * gs + c4 * 4);
    }
}

// ---------------- fragment loaders ----------------
DEV void ldfragA(const float *ak, int m0, uint32_t (*a)[4]) {
#pragma unroll
    for (int mt = 0; mt < 2; mt++) {
        int mo = m0 + mt * 16;
        a[mt][0] = __float_as_uint(ak[mo]);
        a[mt][1] = __float_as_uint(ak[mo + 8]);
        a[mt][2] = __float_as_uint(ak[4 * TS + mo]);
        a[mt][3] = __float_as_uint(ak[4 * TS + mo + 8]);
    }
}
DEV void ldfragB(const float *bk, int n0, uint32_t (*b)[2]) {
#pragma unroll
    for (int nt = 0; nt < 4; nt++) {
        int no = n0 + nt * 8;
        b[nt][0] = __float_as_uint(bk[no]);
        b[nt][1] = __float_as_uint(bk[4 * TS + no]);
    }
}
// B n-major [n][k] stride TSV (V native layout)
DEV void ldfragBn(const float *Bs, int n0, int s, int r, int c, uint32_t (*b)[2]) {
#pragma unroll
    for (int nt = 0; nt < 4; nt++) {
        const float *bn = Bs + (n0 + nt * 8 + r) * TSV + s * 8 + c;
        b[nt][0] = __float_as_uint(bn[0]);
        b[nt][1] = __float_as_uint(bn[4]);
    }
}

// ---------------- 128x128x128 warp-MMA GEMM, 16 warps, warp tile 32x32 ------
// 2-deep software pipeline: fragments for k-step s+1 are issued BEFORE the
// MMAs of k-step s, so the 29-cyc LDS latency hides behind 8 HMMAs.
DEV void wgemm(const float *As, const float *Bs, float (*acc)[4]) {
    int t = threadIdx.x, wid = t >> 5, lane = t & 31;
    int m0 = (wid >> 2) * 32, n0 = (wid & 3) * 32;
    int r = lane >> 2, c = lane & 3;
    uint32_t a[2][2][4], b[2][4][2];
    ldfragA(As + c * TS + r, m0, a[0]);
    ldfragB(Bs + c * TS + r, n0, b[0]);
#pragma unroll
    for (int s = 0; s < 16; s++) {
        int cur = s & 1, nxt = cur ^ 1;
        if (s < 15) {
            ldfragA(As + ((s + 1) * 8 + c) * TS + r, m0, a[nxt]);
            ldfragB(Bs + ((s + 1) * 8 + c) * TS + r, n0, b[nxt]);
        }
#pragma unroll
        for (int mt = 0; mt < 2; mt++)
#pragma unroll
            for (int nt = 0; nt < 4; nt++)
                mma8(acc[mt * 4 + nt], a[cur][mt], b[cur][nt]);
    }
}

// Same, but B is n-major [n][k] stride TSV (reads V in its NATIVE layout).
DEV void wgemm_bn(const float *As, const float *Bs, float (*acc)[4]) {
    int t = threadIdx.x, wid = t >> 5, lane = t & 31;
    int m0 = (wid >> 2) * 32, n0 = (wid & 3) * 32;
    int r = lane >> 2, c = lane & 3;
    uint32_t a[2][2][4], b[2][4][2];
    ldfragA(As + c * TS + r, m0, a[0]);
    ldfragBn(Bs, n0, 0, r, c, b[0]);
#pragma unroll
    for (int s = 0; s < 16; s++) {
        int cur = s & 1, nxt = cur ^ 1;
        if (s < 15) {
            ldfragA(As + ((s + 1) * 8 + c) * TS + r, m0, a[nxt]);
            ldfragBn(Bs, n0, s + 1, r, c, b[nxt]);
        }
#pragma unroll
        for (int mt = 0; mt < 2; mt++)
#pragma unroll
            for (int nt = 0; nt < 4; nt++)
                mma8(acc[mt * 4 + nt], a[cur][mt], b[cur][nt]);
    }
}

DEV void zero_acc(float (*a)[4]) {
#pragma unroll
    for (int i = 0; i < 8; i++)
#pragma unroll
        for (int j = 0; j < 4; j++) a[i][j] = 0.f;
}

DEV float shfl_red(float s) {
    s += __shfl_xor_sync(0xffffffffu, s, 4);
    s += __shfl_xor_sync(0xffffffffu, s, 8);
    s += __shfl_xor_sync(0xffffffffu, s, 16);
    return s;
}

// ---------------- P1: phi_k -> kv / ksum partial slots (flat partition) -----
// smem: W(TS) | bufA(TS: K -> phi) | bufV(TSV: V native) | ksp[4][128]
__global__ __launch_bounds__(512, 1) void k_p1(const float *__restrict__ keys,
                                               const float *__restrict__ V,
                                               const float *__restrict__ feats) {
    extern __shared__ float sm[];
    float *W = sm, *bufA = sm + 128 * TS, *bufV = sm + 2 * 128 * TS;
    float *ksp = sm + 2 * 128 * TS + 128 * TSV;
    uint32_t sb = (uint32_t)__cvta_generic_to_shared(sm);
    uint32_t sbA = sb + TILE_B, sbV = sb + 2u * TILE_B;
    int blk = blockIdx.x, t = threadIdx.x;
    int lo = blk * NT / NBLK, hi = (blk + 1) * NT / NBLK;

    auto kptr = [&](int s) { return keys + (size_t)(s >> 6) * 128 * Ll + (s & 63) * 128; };
    auto vptr = [&](int s) { return V + (size_t)(s >> 6) * 128 * Ll + (s & 63) * 128; };

    load_tile(sb, feats, 128, TS);                 // W   (group A)
    load_tile(sbA, kptr(lo), Ll, TS); cpcommit();  // K0  (group A)
    load_tile(sbV, vptr(lo), Ll, TSV); cpcommit(); // V0  (group B)
    ksp[t] = 0.f;

    int wid = t >> 5, lane = t & 31;
    int m0 = (wid >> 2) * 32, n0 = (wid & 3) * 32;
    int r = lane >> 2, c = lane & 3;
    int wr = wid >> 2;

    float kv[8][4];
    zero_acc(kv);
    int seg = 0;

    for (int s = lo; s < hi; s++) {
        cpwait<1>(); __syncthreads();     // K[s] ready (V may be in flight)

        float pa[8][4];
        zero_acc(pa);
        wgemm(bufA, W, pa);               // D[l][m] = K^T W (HW truncates K,W)
        __syncthreads();                  // K tile fully read

        // epilogue: phi = rna(relu(D*scale)) -> bufA[l][m]; ksum fold
#pragma unroll
        for (int nt = 0; nt < 4; nt++) {
            float s0 = 0.f, s1 = 0.f;
            int Nc = n0 + nt * 8 + 2 * c;
#pragma unroll
            for (int mt = 0; mt < 2; mt++) {
                float *d = pa[mt * 4 + nt];
                int Mr = m0 + mt * 16 + r;
                float2 lo2 = {rna(fmaxf(d[0] * SCALE, 0.f)), rna(fmaxf(d[1] * SCALE, 0.f))};
                float2 hi2 = {rna(fmaxf(d[2] * SCALE, 0.f)), rna(fmaxf(d[3] * SCALE, 0.f))};
                *(float2 *)(bufA + Mr * TS + Nc) = lo2;
                *(float2 *)(bufA + (Mr + 8) * TS + Nc) = hi2;
                s0 += lo2.x + hi2.x;
                s1 += lo2.y + hi2.y;
            }
            s0 = shfl_red(s0);
            s1 = shfl_red(s1);
            if (lane < 4) {
                ksp[wr * 128 + Nc] += s0;
                ksp[wr * 128 + Nc + 1] += s1;
            }
        }
        cpwait<0>();                      // V[s] arrived (this thread)
        __syncthreads();                  // phi + V visible to all

        wgemm_bn(bufA, bufV, kv);         // kv[m][v] += phi^T V^T (V truncated by HW)
        __syncthreads();                  // buffers free

        if (s + 1 < hi) {                 // prefetch next subtile
            load_tile(sbA, kptr(s + 1), Ll, TS); cpcommit();
            load_tile(sbV, vptr(s + 1), Ll, TSV); cpcommit();
        }

        bool fl = (s + 1 == hi) || ((s + 1) >> 6) != (s >> 6);
        if (fl) {                         // flush segment partials (<=2 per block)
            int slot = blk * 2 + seg;
            float *kvp = g_kvpart + (size_t)slot * 16384;
#pragma unroll
            for (int mt = 0; mt < 2; mt++)
#pragma unroll
                for (int nt = 0; nt < 4; nt++) {
                    float *d = kv[mt * 4 + nt];
                    int Mr = m0 + mt * 16 + r, Nc = n0 + nt * 8 + 2 * c;
                    *(float2 *)(kvp + Mr * 128 + Nc) = make_float2(d[0], d[1]);
                    *(float2 *)(kvp + (Mr + 8) * 128 + Nc) = make_float2(d[2], d[3]);
                }
            if (t < 128) g_kspart[slot * 128 + t] =
                ksp[t] + ksp[128 + t] + ksp[256 + t] + ksp[384 + t];
            if (t == 0) g_kvtag[slot] = s >> 6;
            __syncthreads();              // ksp reads done before reset
            ksp[t] = 0.f;
            zero_acc(kv);
            seg++;
        }
    }
    if (t == 0)
        for (int q = seg; q < 2; q++) g_kvtag[blk * 2 + q] = -1;
}

// ---------------- reduce: tagged partials -> kv (rna) + ksum ----------------
__global__ __launch_bounds__(256) void k_red() {
    __shared__ int tags[NSLOT];
    int mg = blockIdx.x, b = blockIdx.y, t = threadIdx.x;
    for (int i = t; i < NSLOT; i += 256) tags[i] = g_kvtag[i];
    __syncthreads();

    int v = (t & 31) * 4, mr = t >> 5;
    float4 a0 = make_float4(0.f, 0.f, 0.f, 0.f), a1 = a0;
    int m0_ = mg * 16 + mr, m1_ = mg * 16 + 8 + mr;
    for (int s = 0; s < NSLOT; s++) {
        if (tags[s] != b) continue;
        const float *base = g_kvpart + (size_t)s * 16384;
        float4 x0 = *(const float4 *)(base + m0_ * 128 + v);
        float4 x1 = *(const float4 *)(base + m1_ * 128 + v);
        a0.x += x0.x; a0.y += x0.y; a0.z += x0.z; a0.w += x0.w;
        a1.x += x1.x; a1.y += x1.y; a1.z += x1.z; a1.w += x1.w;
    }
    a0.x = rna(a0.x); a0.y = rna(a0.y); a0.z = rna(a0.z); a0.w = rna(a0.w);
    a1.x = rna(a1.x); a1.y = rna(a1.y); a1.z = rna(a1.z); a1.w = rna(a1.w);
    *(float4 *)(g_kv + (size_t)b * 16384 + m0_ * 128 + v) = a0;
    *(float4 *)(g_kv + (size_t)b * 16384 + m1_ * 128 + v) = a1;

    if (mg == 0 && t < 128) {
        float ss = 0.f;
        for (int s = 0; s < NSLOT; s++)
            if (tags[s] == b) ss += g_kspart[s * 128 + t];
        g_ksum[b * 128 + t] = ss;
    }
}

// ---------------- P2: phi_q -> out (flat partition, W/KV persistent) --------
// smem: W | KV | R (rotating Q->phi) | ks[128] | denp[4][128] | rden[128]
__global__ __launch_bounds__(512, 1) void k_p2(const float *__restrict__ queries,
                                               const float *__restrict__ feats,
                                               float *__restrict__ out) {
    extern __shared__ float sm[];
    float *W = sm, *KV = sm + 128 * TS, *R = sm + 2 * 128 * TS;
    float *ks = sm + 3 * 128 * TS, *denp = ks + 128, *rden = denp + 512;
    uint32_t sb = (uint32_t)__cvta_generic_to_shared(sm);
    uint32_t sbKV = sb + TILE_B, sbR = sb + 2u * TILE_B;
    uint32_t sbKS = sb + 3u * TILE_B;
    int blk = blockIdx.x, t = threadIdx.x;
    int lo = blk * NT / NBLK, hi = (blk + 1) * NT / NBLK;
    int curb = lo >> 6;

    load_tile(sb, feats, 128, TS);                          // W
    load_tile(sbKV, g_kv + (size_t)curb * 16384, 128, TS);  // kv(batch lo)
    if (t < 32) cp16(sbKS + (uint32_t)t * 16, g_ksum + curb * 128 + t * 4);
    cpcommit();
    {   // Q[lo]
        load_tile(sbR, queries + (size_t)(lo >> 6) * 128 * Ll + (lo & 63) * 128, Ll, TS);
        cpcommit();
    }

    int wid = t >> 5, lane = t & 31;
    int m0 = (wid >> 2) * 32, n0 = (wid & 3) * 32;
    int r = lane >> 2, c = lane & 3;
    int wr = wid >> 2;

    for (int tt = lo; tt < hi; tt++) {
        int b = tt >> 6, l0 = (tt & 63) * 128;
        if (b != curb) {                  // <=1 per block: reload kv/ksum
            load_tile(sbKV, g_kv + (size_t)b * 16384, 128, TS);
            if (t < 32) cp16(sbKS + (uint32_t)t * 16, g_ksum + b * 128 + t * 4);
            cpcommit();
            curb = b;
        }
        cpwait<0>(); __syncthreads();     // Q[tt] (+kv/ks) ready

        float pa[8][4];
        zero_acc(pa);
        wgemm(W, R, pa);                  // D[m][l] = W^T Q (HW truncates W,Q)
        __syncthreads();                  // Q fully read

        // epilogue: phi -> R[m][l]; denominator fold (den[l] = sum_m phi*ks[m])
#pragma unroll
        for (int nt = 0; nt < 4; nt++) {
            float s0 = 0.f, s1 = 0.f;
            int Nc = n0 + nt * 8 + 2 * c;
#pragma unroll
            for (int mt = 0; mt < 2; mt++) {
                float *d = pa[mt * 4 + nt];
                int Mr = m0 + mt * 16 + r;
                float ka = ks[Mr], kb = ks[Mr + 8];
                float2 lo2 = {rna(fmaxf(d[0] * SCALE, 0.f)), rna(fmaxf(d[1] * SCALE, 0.f))};
                float2 hi2 = {rna(fmaxf(d[2] * SCALE, 0.f)), rna(fmaxf(d[3] * SCALE, 0.f))};
                *(float2 *)(R + Mr * TS + Nc) = lo2;
                *(float2 *)(R + (Mr + 8) * TS + Nc) = hi2;
                s0 = fmaf(lo2.x, ka, fmaf(hi2.x, kb, s0));
                s1 = fmaf(lo2.y, ka, fmaf(hi2.y, kb, s1));
            }
            s0 = shfl_red(s0);
            s1 = shfl_red(s1);
            if (lane < 4) {
                denp[wr * 128 + Nc] = s0;
                denp[wr * 128 + Nc + 1] = s1;
            }
        }
        __syncthreads();
        if (t < 128) rden[t] = rcp_nr(denp[t] + denp[128 + t] + denp[256 + t] + denp[384 + t]);

        float oa[8][4];
        zero_acc(oa);
        wgemm(KV, R, oa);                 // D[v][l] = kv^T phi_q
        __syncthreads();                  // R free; rden visible

        if (tt + 1 < hi) {                // prefetch next Q while storing
            int nb = (tt + 1) >> 6, nl = ((tt + 1) & 63) * 128;
            load_tile(sbR, queries + (size_t)nb * 128 * Ll + nl, Ll, TS);
            cpcommit();
        }

        // direct store from fragments: out[v][l] = D * rden[l]
#pragma unroll
        for (int nt = 0; nt < 4; nt++) {
            int Nc = n0 + nt * 8 + 2 * c;
            float2 dd = *(float2 *)(rden + Nc);
#pragma unroll
            for (int mt = 0; mt < 2; mt++) {
                float *d = oa[mt * 4 + nt];
                int Mr = m0 + mt * 16 + r;
                *(float2 *)(out + (size_t)(b * 128 + Mr) * Ll + l0 + Nc) =
                    make_float2(d[0] * dd.x, d[1] * dd.y);
                *(float2 *)(out + (size_t)(b * 128 + Mr + 8) * Ll + l0 + Nc) =
                    make_float2(d[2] * dd.x, d[3] * dd.y);
            }
        }
    }
}

// ---------------- launch ----------------
extern "C" void kernel_launch(void *const *d_in, const int *in_sizes, int n_in,
                              void *d_out, int out_size) {
    (void)in_sizes; (void)n_in; (void)out_size;
    const float *keys = (const float *)d_in[0];
    const float *values = (const float *)d_in[1];
    const float *queries = (const float *)d_in[2];
    const float *feats = (const float *)d_in[3];
    float *out = (float *)d_out;

    constexpr int SM_P1 = 2 * TILE_B + TILEV_B + 512 * 4;          // 208896
    constexpr int SM_P2 = 3 * TILE_B + (128 + 512 + 128) * 4;      // 211968

    cudaFuncSetAttribute(k_p1, cudaFuncAttributeMaxDynamicSharedMemorySize, SM_P1);
    cudaFuncSetAttribute(k_p2, cudaFuncAttributeMaxDynamicSharedMemorySize, SM_P2);

    k_p1<<<NBLK, 512, SM_P1>>>(keys, values, feats);
    k_red<<<dim3(8, Bb), 256>>>();
    k_p2<<<NBLK, 512, SM_P2>>>(queries, feats, out);
}

// round 17
// speedup vs baseline: 1.5098x; 1.5098x over previous
#include <cuda_runtime.h>
#include <cuda_fp16.h>
#include <cstdint>
#include <cstddef>

#define DEV static __device__ __forceinline__

constexpr int Bb = 16, Ll = 8192;
constexpr int NBLK = 152;              // flat blocks (= GB300 SM count)
constexpr int NSLOT = NBLK * 2;        // kv partial slots (2 per block)
constexpr int NT = 1024;               // total (batch, l-tile) units: 16*64
constexpr float SCALE = 0.08838834764831845f; // 1/sqrt(128)
constexpr int SSG = 132;  // fp32 staging tile row stride (floats) -> 33 x 16B units
constexpr int TH = 136;   // fp16 tile row stride (halves)         -> 17 x 16B units

// smem byte offsets (P1)
constexpr int O_STG = 0;                       // fp32 stage: 128*132*4 = 67584
constexpr int O_W = 67584;                     // W16:  128*136*2 = 34816
constexpr int O_A = 102400;                    // K/phi16
constexpr int O_V = 137216;                    // V16
constexpr int O_KSP = 172032;                  // ksp: 512 floats
constexpr int SM_P1 = 174080;
// P2 reuses O_STG/O_W, KV at O_A, R(Q/phi) at O_V
constexpr int O_KS = 172032;                   // ks: 128 floats
constexpr int O_DENP = 172544;                 // denp: 512 floats
constexpr int O_RDEN = 174592;                 // rden: 128 floats
constexpr int SM_P2 = 175104;

// ---------------- scratch (device globals; no allocation) ----------------
__device__ __align__(16) float g_kvpart[(size_t)NSLOT * 16384];
__device__ __align__(16) float g_kspart[NSLOT * 128];
__device__ int g_kvtag[NSLOT];
__device__ __align__(16) __half g_kv16[Bb * 128 * 128]; // kv: [b][m][v] fp16
__device__ __align__(16) float g_ksum[Bb * 128];

// ---------------- helpers ----------------
DEV float rcp_nr(float x) { float r; asm("rcp.approx.f32 %0,%1;" : "=f"(r) : "f"(x)); return r * (2.0f - x * r); }
DEV void cp16(uint32_t s, const void *g) { asm volatile("cp.async.ca.shared.global [%0],[%1],16;" :: "r"(s), "l"(g)); }
DEV void cpcommit() { asm volatile("cp.async.commit_group;"); }
template <int N> DEV void cpwait() { asm volatile("cp.async.wait_group %0;" :: "n"(N)); }

// fp16 m16n8k16 mma, fp32 accumulate (legal on compute_103; tensor pipe)
DEV void mma16(float *d, const uint32_t *a, const uint32_t *b) {
    asm volatile("mma.sync.aligned.m16n8k16.row.col.f32.f16.f16.f32 "
                 "{%0,%1,%2,%3}, {%4,%5,%6,%7}, {%8,%9}, {%0,%1,%2,%3};"
                 : "+f"(d[0]), "+f"(d[1]), "+f"(d[2]), "+f"(d[3])
                 : "r"(a[0]), "r"(a[1]), "r"(a[2]), "r"(a[3]), "r"(b[0]), "r"(b[1]));
}
DEV void ldsm4(uint32_t addr, uint32_t *d) {
    asm volatile("ldmatrix.sync.aligned.m8n8.x4.shared.b16 {%0,%1,%2,%3}, [%4];"
                 : "=r"(d[0]), "=r"(d[1]), "=r"(d[2]), "=r"(d[3]) : "r"(addr));
}
DEV void ldsm4t(uint32_t addr, uint32_t *d) {
    asm volatile("ldmatrix.sync.aligned.m8n8.x4.trans.shared.b16 {%0,%1,%2,%3}, [%4];"
                 : "=r"(d[0]), "=r"(d[1]), "=r"(d[2]), "=r"(d[3]) : "r"(addr));
}

// Load 128x128 fp32 tile (global row stride gs floats) -> smem stage (stride SSG).
DEV void load_stage(uint32_t sb, const float *g, size_t gs) {
    int t = threadIdx.x, c4 = t & 31, r0 = t >> 5;
#pragma unroll
    for (int i = 0; i < 8; i++) {
        int row = i * 16 + r0;
        cp16(sb + (uint32_t)(row * SSG * 4) + (uint32_t)c4 * 16, g + (size_t)row * gs + c4 * 4);
    }
}
// Load 128x128 fp16 tile (global contiguous rows of 128 halves) -> smem (stride TH).
DEV void load_tile_h(uint32_t sb, const __half *g) {
    int t = threadIdx.x, chunk = t & 15, r0 = t >> 4;
#pragma unroll
    for (int i = 0; i < 4; i++) {
        int row = i * 32 + r0;
        cp16(sb + (uint32_t)(row * TH * 2) + (uint32_t)chunk * 16, g + (size_t)row * 128 + chunk * 8);
    }
}
// Convert fp32 stage -> fp16 tile.
DEV void cvt_tile(const float *stg, __half *dst) {
    int t = threadIdx.x;
#pragma unroll
    for (int i = 0; i < 8; i++) {
        int idx = t + i * 512;
        int row = idx >> 5, c4 = (idx & 31) * 4;
        float4 v = *(const float4 *)(stg + row * SSG + c4);
        *(__half2 *)(dst + row * TH + c4) = __floats2half2_rn(v.x, v.y);
        *(__half2 *)(dst + row * TH + c4 + 2) = __floats2half2_rn(v.z, v.w);
    }
}
// Convert fp32 global (row stride 128) -> fp16 tile directly (for W; L2-resident).
DEV void cvt_direct(const float *g, __half *dst) {
    int t = threadIdx.x;
#pragma unroll
    for (int i = 0; i < 8; i++) {
        int idx = t + i * 512;
        int row = idx >> 5, c4 = (idx & 31) * 4;
        float4 v = *(const float4 *)(g + row * 128 + c4);
        *(__half2 *)(dst + row * TH + c4) = __floats2half2_rn(v.x, v.y);
        *(__half2 *)(dst + row * TH + c4 + 2) = __floats2half2_rn(v.z, v.w);
    }
}

// ---------------- 128x128x128 GEMM, fp16 frags via ldmatrix ----------------
// acc(+)= A^T*B. A: [k][m] halves stride TH (trans-ldmatrix).
// tt: B [k][n] stride TH (trans).  tn: B [n][k] stride TH (natural, V/kv-native).
DEV void wgemm16_tt(uint32_t A, uint32_t B, float (*acc)[4]) {
    int t = threadIdx.x, wid = t >> 5, lane = t & 31;
    int m0 = (wid >> 2) * 32, n0 = (wid & 3) * 32;
    int q = lane >> 3, rr = lane & 7;
    uint32_t aA = A + (uint32_t)(((((q >> 1) * 8 + rr) * TH) + m0 + (q & 1) * 8) * 2);
    uint32_t bA = B + (uint32_t)(((((q & 1) * 8 + rr) * TH) + n0 + (q >> 1) * 8) * 2);
#pragma unroll
    for (int s = 0; s < 8; s++) {
        uint32_t a0[4], a1[4], b0[4], b1[4];
        ldsm4t(aA, a0); ldsm4t(aA + 32, a1);        // m0, m0+16
        ldsm4t(bA, b0); ldsm4t(bA + 32, b1);        // n0, n0+16
        aA += 16 * TH * 2; bA += 16 * TH * 2;
        mma16(acc[0], a0, b0); mma16(acc[1], a0, b0 + 2);
        mma16(acc[2], a0, b1); mma16(acc[3], a0, b1 + 2);
        mma16(acc[4], a1, b0); mma16(acc[5], a1, b0 + 2);
        mma16(acc[6], a1, b1); mma16(acc[7], a1, b1 + 2);
    }
}
DEV void wgemm16_tn(uint32_t A, uint32_t B, float (*acc)[4]) {
    int t = threadIdx.x, wid = t >> 5, lane = t & 31;
    int m0 = (wid >> 2) * 32, n0 = (wid & 3) * 32;
    int q = lane >> 3, rr = lane & 7;
    uint32_t aA = A + (uint32_t)(((((q >> 1) * 8 + rr) * TH) + m0 + (q & 1) * 8) * 2);
    uint32_t bA0 = B + (uint32_t)((((n0 + (q >> 1) * 8 + rr) * TH) + (q & 1) * 8) * 2);
    uint32_t bA1 = bA0 + 16 * TH * 2;               // n0+16
#pragma unroll
    for (int s = 0; s < 8; s++) {
        uint32_t a0[4], a1[4], b0[4], b1[4];
        ldsm4t(aA, a0); ldsm4t(aA + 32, a1);
        ldsm4(bA0, b0); ldsm4(bA1, b1);
        aA += 16 * TH * 2; bA0 += 32; bA1 += 32;    // k advances along rows
        mma16(acc[0], a0, b0); mma16(acc[1], a0, b0 + 2);
        mma16(acc[2], a0, b1); mma16(acc[3], a0, b1 + 2);
        mma16(acc[4], a1, b0); mma16(acc[5], a1, b0 + 2);
        mma16(acc[6], a1, b1); mma16(acc[7], a1, b1 + 2);
    }
}

DEV void zero_acc(float (*a)[4]) {
#pragma unroll
    for (int i = 0; i < 8; i++)
#pragma unroll
        for (int j = 0; j < 4; j++) a[i][j] = 0.f;
}
DEV float shfl_red(float s) {
    s += __shfl_xor_sync(0xffffffffu, s, 4);
    s += __shfl_xor_sync(0xffffffffu, s, 8);
    s += __shfl_xor_sync(0xffffffffu, s, 16);
    return s;
}

// ---------------- P1: phi_k -> kv / ksum partial slots (flat partition) -----
__global__ __launch_bounds__(512, 1) void k_p1(const float *__restrict__ keys,
                                               const float *__restrict__ V,
                                               const float *__restrict__ feats) {
    extern __shared__ char smc[];
    float *stg = (float *)(smc + O_STG);
    __half *W16 = (__half *)(smc + O_W), *A16 = (__half *)(smc + O_A), *V16 = (__half *)(smc + O_V);
    float *ksp = (float *)(smc + O_KSP);
    uint32_t sb = (uint32_t)__cvta_generic_to_shared(smc);
    uint32_t uSTG = sb + O_STG, uW = sb + O_W, uA = sb + O_A, uV = sb + O_V;
    int blk = blockIdx.x, t = threadIdx.x;
    int lo = blk * NT / NBLK, hi = (blk + 1) * NT / NBLK;

    auto kptr = [&](int s) { return keys + (size_t)(s >> 6) * 128 * Ll + (s & 63) * 128; };
    auto vptr = [&](int s) { return V + (size_t)(s >> 6) * 128 * Ll + (s & 63) * 128; };

    load_stage(uSTG, kptr(lo), Ll); cpcommit();    // K0 -> stage (async)
    cvt_direct(feats, W16);                        // W fp32->fp16 (overlaps K0 load)
    ksp[t] = 0.f;

    int wid = t >> 5, lane = t & 31;
    int m0 = (wid >> 2) * 32, n0 = (wid & 3) * 32;
    int r = lane >> 2, c = lane & 3;
    int wr = wid >> 2;

    float kv[8][4];
    zero_acc(kv);
    int seg = 0;

    for (int s = lo; s < hi; s++) {
        cpwait<0>(); __syncthreads();     // K[s] in stage; W16 ready (first iter)
        cvt_tile(stg, A16);               // K -> fp16 tile
        __syncthreads();                  // A16 ready; stage free
        load_stage(uSTG, vptr(s), Ll); cpcommit();  // V[s] load overlaps GEMM1

        float pa[8][4];
        zero_acc(pa);
        wgemm16_tt(uA, uW, pa);           // D[l][m] = K^T W
        __syncthreads();                  // A16 fully read

        // epilogue: phi = fp16(relu(D*scale)) -> A16[l][m]; ksum fold
#pragma unroll
        for (int nt = 0; nt < 4; nt++) {
            float s0 = 0.f, s1 = 0.f;
            int Nc = n0 + nt * 8 + 2 * c;
#pragma unroll
            for (int mt = 0; mt < 2; mt++) {
                float *d = pa[mt * 4 + nt];
                int Mr = m0 + mt * 16 + r;
                __half2 hlo = __floats2half2_rn(fmaxf(d[0] * SCALE, 0.f), fmaxf(d[1] * SCALE, 0.f));
                __half2 hhi = __floats2half2_rn(fmaxf(d[2] * SCALE, 0.f), fmaxf(d[3] * SCALE, 0.f));
                *(__half2 *)(A16 + Mr * TH + Nc) = hlo;
                *(__half2 *)(A16 + (Mr + 8) * TH + Nc) = hhi;
                float2 lo2 = __half22float2(hlo), hi2 = __half22float2(hhi);
                s0 += lo2.x + hi2.x;
                s1 += lo2.y + hi2.y;
            }
            s0 = shfl_red(s0);
            s1 = shfl_red(s1);
            if (lane < 4) {
                ksp[wr * 128 + Nc] += s0;
                ksp[wr * 128 + Nc + 1] += s1;
            }
        }
        cpwait<0>(); __syncthreads();     // phi visible; V[s] in stage
        cvt_tile(stg, V16);               // V -> fp16 tile
        __syncthreads();                  // V16 ready; stage free
        if (s + 1 < hi) { load_stage(uSTG, kptr(s + 1), Ll); cpcommit(); } // overlaps GEMM2

        wgemm16_tn(uA, uV, kv);           // kv[m][v] += phi^T V (V native [v][l])
        __syncthreads();

        bool fl = (s + 1 == hi) || ((s + 1) >> 6) != (s >> 6);
        if (fl) {                         // flush segment partials (<=2 per block)
            int slot = blk * 2 + seg;
            float *kvp = g_kvpart + (size_t)slot * 16384;
#pragma unroll
            for (int mt = 0; mt < 2; mt++)
#pragma unroll
                for (int nt = 0; nt < 4; nt++) {
                    float *d = kv[mt * 4 + nt];
                    int Mr = m0 + mt * 16 + r, Nc = n0 + nt * 8 + 2 * c;
                    *(float2 *)(kvp + Mr * 128 + Nc) = make_float2(d[0], d[1]);
                    *(float2 *)(kvp + (Mr + 8) * 128 + Nc) = make_float2(d[2], d[3]);
                }
            if (t < 128) g_kspart[slot * 128 + t] =
                ksp[t] + ksp[128 + t] + ksp[256 + t] + ksp[384 + t];
            if (t == 0) g_kvtag[slot] = s >> 6;
            __syncthreads();              // ksp reads done before reset
            ksp[t] = 0.f;
            zero_acc(kv);
            seg++;
        }
    }
    if (t == 0)
        for (int q = seg; q < 2; q++) g_kvtag[blk * 2 + q] = -1;
}

// ---------------- reduce: tagged partials -> kv fp16 + ksum ----------------
__global__ __launch_bounds__(256) void k_red() {
    __shared__ int tags[NSLOT];
    int mg = blockIdx.x, b = blockIdx.y, t = threadIdx.x;
    for (int i = t; i < NSLOT; i += 256) tags[i] = g_kvtag[i];
    __syncthreads();

    int v = (t & 31) * 4, mr = t >> 5;
    float4 a0 = make_float4(0.f, 0.f, 0.f, 0.f), a1 = a0;
    int m0_ = mg * 16 + mr, m1_ = mg * 16 + 8 + mr;
    for (int s = 0; s < NSLOT; s++) {
        if (tags[s] != b) continue;
        const float *base = g_kvpart + (size_t)s * 16384;
        float4 x0 = *(const float4 *)(base + m0_ * 128 + v);
        float4 x1 = *(const float4 *)(base + m1_ * 128 + v);
        a0.x += x0.x; a0.y += x0.y; a0.z += x0.z; a0.w += x0.w;
        a1.x += x1.x; a1.y += x1.y; a1.z += x1.z; a1.w += x1.w;
    }
    __half *dst = g_kv16 + (size_t)b * 16384;
    *(__half2 *)(dst + m0_ * 128 + v) = __floats2half2_rn(a0.x, a0.y);
    *(__half2 *)(dst + m0_ * 128 + v + 2) = __floats2half2_rn(a0.z, a0.w);
    *(__half2 *)(dst + m1_ * 128 + v) = __floats2half2_rn(a1.x, a1.y);
    *(__half2 *)(dst + m1_ * 128 + v + 2) = __floats2half2_rn(a1.z, a1.w);

    if (mg == 0 && t < 128) {
        float ss = 0.f;
        for (int s = 0; s < NSLOT; s++)
            if (tags[s] == b) ss += g_kspart[s * 128 + t];
        g_ksum[b * 128 + t] = ss;
    }
}

// ---------------- P2: phi_q -> out (flat partition, W/KV persistent) --------
__global__ __launch_bounds__(512, 1) void k_p2(const float *__restrict__ queries,
                                               const float *__restrict__ feats,
                                               float *__restrict__ out) {
    extern __shared__ char smc[];
    float *stg = (float *)(smc + O_STG);
    __half *W16 = (__half *)(smc + O_W), *KV16 = (__half *)(smc + O_A), *R16 = (__half *)(smc + O_V);
    float *ks = (float *)(smc + O_KS), *denp = (float *)(smc + O_DENP), *rden = (float *)(smc + O_RDEN);
    uint32_t sb = (uint32_t)__cvta_generic_to_shared(smc);
    uint32_t uSTG = sb + O_STG, uW = sb + O_W, uKV = sb + O_A, uR = sb + O_V;
    uint32_t uKS = sb + O_KS;
    int blk = blockIdx.x, t = threadIdx.x;
    int lo = blk * NT / NBLK, hi = (blk + 1) * NT / NBLK;
    int curb = lo >> 6;

    load_tile_h(uKV, g_kv16 + (size_t)curb * 16384);        // kv fp16 direct
    if (t < 32) cp16(uKS + (uint32_t)t * 16, g_ksum + curb * 128 + t * 4);
    load_stage(uSTG, queries + (size_t)curb * 128 * Ll + (lo & 63) * 128, Ll);
    cpcommit();
    cvt_direct(feats, W16);                                 // W (overlaps loads)

    int wid = t >> 5, lane = t & 31;
    int m0 = (wid >> 2) * 32, n0 = (wid & 3) * 32;
    int r = lane >> 2, c = lane & 3;
    int wr = wid >> 2;

    for (int tt = lo; tt < hi; tt++) {
        int b = tt >> 6, l0 = (tt & 63) * 128;
        if (b != curb) {                  // <=1 per block: reload kv/ksum
            load_tile_h(uKV, g_kv16 + (size_t)b * 16384);
            if (t < 32) cp16(uKS + (uint32_t)t * 16, g_ksum + b * 128 + t * 4);
            cpcommit();
            curb = b;
        }
        cpwait<0>(); __syncthreads();     // Q[tt] in stage (+kv/ks)
        cvt_tile(stg, R16);               // Q -> fp16 tile
        __syncthreads();                  // R16 ready; stage free
        if (tt + 1 < hi) {                // prefetch next Q (overlaps both GEMMs)
            int nb = (tt + 1) >> 6, nl = ((tt + 1) & 63) * 128;
            load_stage(uSTG, queries + (size_t)nb * 128 * Ll + nl, Ll);
            cpcommit();
        }

        float pa[8][4];
        zero_acc(pa);
        wgemm16_tt(uW, uR, pa);           // D[m][l] = W^T Q
        __syncthreads();                  // Q16 fully read

        // epilogue: phi -> R16[m][l]; denominator fold (den[l] = sum_m phi*ks[m])
#pragma unroll
        for (int nt = 0; nt < 4; nt++) {
            float s0 = 0.f, s1 = 0.f;
            int Nc = n0 + nt * 8 + 2 * c;
#pragma unroll
            for (int mt = 0; mt < 2; mt++) {
                float *d = pa[mt * 4 + nt];
                int Mr = m0 + mt * 16 + r;
                float ka = ks[Mr], kb = ks[Mr + 8];
                __half2 hlo = __floats2half2_rn(fmaxf(d[0] * SCALE, 0.f), fmaxf(d[1] * SCALE, 0.f));
                __half2 hhi = __floats2half2_rn(fmaxf(d[2] * SCALE, 0.f), fmaxf(d[3] * SCALE, 0.f));
                *(__half2 *)(R16 + Mr * TH + Nc) = hlo;
                *(__half2 *)(R16 + (Mr + 8) * TH + Nc) = hhi;
                float2 lo2 = __half22float2(hlo), hi2 = __half22float2(hhi);
                s0 = fmaf(lo2.x, ka, fmaf(hi2.x, kb, s0));
                s1 = fmaf(lo2.y, ka, fmaf(hi2.y, kb, s1));
            }
            s0 = shfl_red(s0);
            s1 = shfl_red(s1);
            if (lane < 4) {
                denp[wr * 128 + Nc] = s0;
                denp[wr * 128 + Nc + 1] = s1;
            }
        }
        __syncthreads();
        if (t < 128) rden[t] = rcp_nr(denp[t] + denp[128 + t] + denp[256 + t] + denp[384 + t]);

        float oa[8][4];
        zero_acc(oa);
        wgemm16_tt(uKV, uR, oa);          // D[v][l] = kv^T phi_q
        __syncthreads();                  // R16 free; rden visible

        // direct store from fragments: out[v][l] = D * rden[l]
#pragma unroll
        for (int nt = 0; nt < 4; nt++) {
            int Nc = n0 + nt * 8 + 2 * c;
            float2 dd = *(float2 *)(rden + Nc);
#pragma unroll
            for (int mt = 0; mt < 2; mt++) {
                float *d = oa[mt * 4 + nt];
                int Mr = m0 + mt * 16 + r;
                *(float2 *)(out + (size_t)(b * 128 + Mr) * Ll + l0 + Nc) =
                    make_float2(d[0] * dd.x, d[1] * dd.y);
                *(float2 *)(out + (size_t)(b * 128 + Mr + 8) * Ll + l0 + Nc) =
                    make_float2(d[2] * dd.x, d[3] * dd.y);
            }
        }
    }
}

// ---------------- launch ----------------
extern "C" void kernel_launch(void *const *d_in, const int *in_sizes, int n_in,
                              void *d_out, int out_size) {
    (void)in_sizes; (void)n_in; (void)out_size;
    const float *keys = (const float *)d_in[0];
    const float *values = (const float *)d_in[1];
    const float *queries = (const float *)d_in[2];
    const float *feats = (const float *)d_in[3];
    float *out = (float *)d_out;

    cudaFuncSetAttribute(k_p1, cudaFuncAttributeMaxDynamicSharedMemorySize, SM_P1);
    cudaFuncSetAttribute(k_p2, cudaFuncAttributeMaxDynamicSharedMemorySize, SM_P2);

    k_p1<<<NBLK, 512, SM_P1>>>(keys, values, feats);
    k_red<<<dim3(8, Bb), 256>>>();
    k_p2<<<NBLK, 512, SM_P2>>>(queries, feats, out);
}